// round 14
// baseline (speedup 1.0000x reference)
#include <cuda_runtime.h>
#include <cuda_bf16.h>
#include <mma.h>
#include <cstdint>

using namespace nvcuda;

// D-MPNN on GB300. Round 14: R13 + coalesced layer epilogue (D staged via
// smem, STG.128 row-contiguous writes). Everything else unchanged.

#define NN 200000
#define NE 800000
#define HD 128
#define NGB 2000
#define SCANB 512
#define NSCAN ((NN + SCANB - 1) / SCANB)

__device__ float g_x[(size_t)NN * HD];
__device__ float g_he[(size_t)NE * HD];
__device__ float g_agg[(size_t)NN * HD];
__device__ float g_wrp[HD];
__device__ float g_wf[28 * HD];
__device__ int g_deg[NN];
__device__ int g_off[NN];
__device__ int g_cursor[NN];
__device__ int g_csr[NE];
__device__ int g_bsum[NSCAN];

__device__ __forceinline__ __nv_bfloat162 pack_hi(float a, float b) {
    return __nv_bfloat162(__float2bfloat16_rn(a), __float2bfloat16_rn(b));
}
__device__ __forceinline__ __nv_bfloat162 pack_lo(float a, float b, __nv_bfloat162 hi) {
    return __nv_bfloat162(__float2bfloat16_rn(a - __bfloat162float(hi.x)),
                          __float2bfloat16_rn(b - __bfloat162float(hi.y)));
}
__device__ __forceinline__ uint32_t b2u(__nv_bfloat162 v) {
    return *reinterpret_cast<uint32_t*>(&v);
}
__device__ __forceinline__ uint32_t smem_u32(const void* p) {
    uint32_t a;
    asm("{ .reg .u64 t; cvta.to.shared.u64 t, %1; cvt.u32.u64 %0, t; }" : "=r"(a) : "l"(p));
    return a;
}
__device__ __forceinline__ void ldsm_x4(uint32_t* r, uint32_t addr) {
    asm volatile("ldmatrix.sync.aligned.m8n8.x4.shared.b16 {%0,%1,%2,%3}, [%4];"
                 : "=r"(r[0]), "=r"(r[1]), "=r"(r[2]), "=r"(r[3]) : "r"(addr));
}
__device__ __forceinline__ void mma16816(float* d, const uint32_t* a, uint32_t b0, uint32_t b1) {
    asm volatile("mma.sync.aligned.m16n8k16.row.col.f32.bf16.bf16.f32 "
                 "{%0,%1,%2,%3},{%4,%5,%6,%7},{%8,%9},{%0,%1,%2,%3};"
                 : "+f"(d[0]), "+f"(d[1]), "+f"(d[2]), "+f"(d[3])
                 : "r"(a[0]), "r"(a[1]), "r"(a[2]), "r"(a[3]), "r"(b0), "r"(b1));
}
__device__ __forceinline__ void cp16(uint32_t smem, const void* g) {
    asm volatile("cp.async.cg.shared.global [%0], [%1], 16;" :: "r"(smem), "l"(g));
}

// ---------------------------------------------------------------- CSR build
__global__ void zero_deg_kernel() {
    int i = blockIdx.x * blockDim.x + threadIdx.x;
    if (i < NN) g_deg[i] = 0;
}
__global__ void deg_count_kernel(const int* __restrict__ dst) {
    int k = blockIdx.x * blockDim.x + threadIdx.x;
    if (k < NE) atomicAdd(&g_deg[dst[k]], 1);
}
__global__ void scan_a_kernel() {
    __shared__ int s[SCANB];
    int t = threadIdx.x;
    int n = blockIdx.x * SCANB + t;
    s[t] = (n < NN) ? g_deg[n] : 0;
    __syncthreads();
    for (int o = SCANB / 2; o > 0; o >>= 1) {
        if (t < o) s[t] += s[t + o];
        __syncthreads();
    }
    if (t == 0) g_bsum[blockIdx.x] = s[0];
}
__global__ void scan_b_kernel() {
    __shared__ int s[512];
    int t = threadIdx.x;
    int v = (t < NSCAN) ? g_bsum[t] : 0;
    s[t] = v;
    __syncthreads();
    for (int o = 1; o < 512; o <<= 1) {
        int x = (t >= o) ? s[t - o] : 0;
        __syncthreads();
        s[t] += x;
        __syncthreads();
    }
    if (t < NSCAN) g_bsum[t] = s[t] - v;
}
__global__ void scan_c_kernel() {
    __shared__ int s[SCANB];
    int t = threadIdx.x;
    int n = blockIdx.x * SCANB + t;
    int val = (n < NN) ? g_deg[n] : 0;
    s[t] = val;
    __syncthreads();
    for (int o = 1; o < SCANB; o <<= 1) {
        int x = (t >= o) ? s[t - o] : 0;
        __syncthreads();
        s[t] += x;
        __syncthreads();
    }
    if (n < NN) {
        int off = g_bsum[blockIdx.x] + s[t] - val;
        g_off[n] = off;
        g_cursor[n] = off;
    }
}
__global__ void csr_fill_kernel(const int* __restrict__ dst) {
    int k = blockIdx.x * blockDim.x + threadIdx.x;
    if (k < NE) {
        int pos = atomicAdd(&g_cursor[dst[k]], 1);
        g_csr[pos] = k;
    }
}

// ---------------------------------------------------------------- Wf = W_emb @ W_init[:128]
__global__ void __launch_bounds__(128) wfuse_kernel(
    const float* __restrict__ Wemb, const float* __restrict__ Winit)
{
    __shared__ float sWe[28 * 128];
    int n = threadIdx.x;
    for (int i = n; i < 28 * 128; i += 128) sWe[i] = Wemb[i];
    __syncthreads();
    float acc[28];
#pragma unroll
    for (int a = 0; a < 28; ++a) acc[a] = 0.f;
    for (int k = 0; k < 128; ++k) {
        float wv = Winit[k * 128 + n];
#pragma unroll
        for (int a = 0; a < 28; ++a) acc[a] += sWe[a * 128 + k] * wv;
    }
#pragma unroll
    for (int a = 0; a < 28; ++a) g_wf[a * 128 + n] = acc[a];
}

// ---------------------------------------------------------------- Z = h @ Wf + b
__global__ void __launch_bounds__(128) z_kernel(
    const float* __restrict__ h, const float* __restrict__ binit)
{
    __shared__ float sh[64 * 28];
    int n0 = blockIdx.x * 64;
    int tid = threadIdx.x;
    for (int idx = tid; idx < 64 * 28; idx += 128)
        sh[idx] = h[(size_t)n0 * 28 + idx];
    __syncthreads();
    float w[28];
#pragma unroll
    for (int i = 0; i < 28; ++i) w[i] = g_wf[i * HD + tid];
    float b = binit[tid];
    for (int n = 0; n < 64; ++n) {
        float acc = b;
#pragma unroll
        for (int i = 0; i < 28; ++i) acc += sh[n * 28 + i] * w[i];
        g_x[(size_t)(n0 + n) * HD + tid] = acc;
    }
}

// ---------------------------------------------------------------- he0 = relu(Z[src] + e@W2)
__global__ void __launch_bounds__(256) init_combine_kernel(
    const float* __restrict__ Winit, const float* __restrict__ eAttr,
    const int* __restrict__ src)
{
    __shared__ float sW2[6 * 128];
    int tid = threadIdx.x;
    for (int i = tid; i < 6 * 128; i += 256) sW2[i] = Winit[128 * 128 + i];
    __syncthreads();

    int k = blockIdx.x * 8 + (tid >> 5);
    int lane = tid & 31;
    int s = __ldg(&src[k]);
    float ev[6];
#pragma unroll
    for (int j = 0; j < 6; ++j) ev[j] = __ldg(&eAttr[(size_t)k * 6 + j]);
    float4 z = *(const float4*)&g_x[(size_t)s * HD + lane * 4];
#pragma unroll
    for (int j = 0; j < 6; ++j) {
        float4 w2 = *(const float4*)&sW2[j * 128 + lane * 4];
        z.x += ev[j] * w2.x; z.y += ev[j] * w2.y;
        z.z += ev[j] * w2.z; z.w += ev[j] * w2.w;
    }
    z.x = fmaxf(z.x, 0.f); z.y = fmaxf(z.y, 0.f);
    z.z = fmaxf(z.z, 0.f); z.w = fmaxf(z.w, 0.f);
    *(float4*)&g_he[(size_t)k * HD + lane * 4] = z;
}

// ---------------------------------------------------------------- layer GEMM
// TE=32, cp.async-staged raw rows, mma.sync register-W, bf16 hi/lo 3-term,
// D staged through smem -> coalesced STG.128 epilogue.
#define LTE 32
#define LNT (NE / LTE)                  // 25000
#define RAW_LD 132
#define RAW_SZ (LTE * RAW_LD)
#define LA_SZ (LTE * 136)               // halves per A component
#define SD_LD 132                       // D staging stride (floats)
// smem: rawHe[2] | rawAgg[2] | (Ahi|Alo == sD region) | bias
#define SMEM_LAYER (4 * RAW_SZ * 4 + 2 * LA_SZ * 2 + 128 * 4)   // 85,504

__global__ void __launch_bounds__(256, 2) layer_kernel(
    const float* __restrict__ W, const float* __restrict__ bias,
    const int* __restrict__ src)
{
    extern __shared__ char sm[];
    float* rawHe = (float*)sm;                        // [2][RAW_SZ]
    float* rawAgg = rawHe + 2 * RAW_SZ;               // [2][RAW_SZ]
    __nv_bfloat16* sAhi = (__nv_bfloat16*)(rawAgg + 2 * RAW_SZ);
    __nv_bfloat16* sAlo = sAhi + LA_SZ;
    float* sD = (float*)sAhi;                         // aliases A (dead after MMA)
    float* sBias = (float*)(sAlo + LA_SZ);
    uint32_t rawHe_u = smem_u32(rawHe);
    uint32_t rawAgg_u = smem_u32(rawAgg);
    uint32_t sAhi_u = smem_u32(sAhi);
    uint32_t sAlo_u = smem_u32(sAlo);

    int tid = threadIdx.x;
    int w = tid >> 5, l = tid & 31;
    int ncb = w * 16;

    // ---- W into registers (once per block) ----
    uint32_t Bh[8][2][2], Bl[8][2][2];
    {
        int kq = (l & 3) * 2;
        int nn = l >> 2;
#pragma unroll
        for (int kt = 0; kt < 8; ++kt)
#pragma unroll
            for (int j = 0; j < 2; ++j) {
                int n = ncb + j * 8 + nn;
#pragma unroll
                for (int hhf = 0; hhf < 2; ++hhf) {
                    int k0 = kt * 16 + hhf * 8 + kq;
                    float w0 = __ldg(&W[k0 * 128 + n]);
                    float w1 = __ldg(&W[(k0 + 1) * 128 + n]);
                    __nv_bfloat162 hi = pack_hi(w0, w1);
                    Bh[kt][j][hhf] = b2u(hi);
                    Bl[kt][j][hhf] = b2u(pack_lo(w0, w1, hi));
                }
            }
    }
    if (tid < 128) sBias[tid] = __ldg(&bias[tid]);

    int quad = l >> 3;
    int arow = (l & 7) + ((quad & 1) ? 8 : 0);
    int acol = (quad >= 2) ? 8 : 0;
    int gr = tid >> 3;                  // row 0..31
    int gseg = tid & 7;                 // 16-float segment

    auto issue = [&](int t, int p, int sIdx) {
        int e0 = t * LTE;
        const float* gh = &g_he[(size_t)(e0 + gr) * HD + gseg * 16];
        const float* ga = &g_agg[(size_t)sIdx * HD + gseg * 16];
        uint32_t dh = rawHe_u + (uint32_t)((p * RAW_SZ + gr * RAW_LD + gseg * 16) * 4);
        uint32_t da = rawAgg_u + (uint32_t)((p * RAW_SZ + gr * RAW_LD + gseg * 16) * 4);
#pragma unroll
        for (int c = 0; c < 4; ++c) {
            cp16(dh + 16 * c, gh + 4 * c);
            cp16(da + 16 * c, ga + 4 * c);
        }
        asm volatile("cp.async.commit_group;" ::: "memory");
    };

    int t = blockIdx.x;
    int p = 0;
    int sCur = (t < LNT) ? __ldg(&src[t * LTE + gr]) : 0;
    int sNext = (t + gridDim.x < LNT) ? __ldg(&src[(t + gridDim.x) * LTE + gr]) : 0;
    if (t < LNT) issue(t, 0, sCur);

    for (; t < LNT; ) {
        int tn = t + gridDim.x;
        int e0 = t * LTE;

        if (tn < LNT) {
            issue(tn, p ^ 1, sNext);
            sNext = (tn + gridDim.x < LNT) ? __ldg(&src[(tn + gridDim.x) * LTE + gr]) : 0;
            asm volatile("cp.async.wait_group 1;" ::: "memory");
        } else {
            asm volatile("cp.async.wait_group 0;" ::: "memory");
        }
        __syncthreads();

        // ---- convert: m = agg - he(rev) -> A hi/lo ----
        {
            const float* ph = &rawHe[p * RAW_SZ + (gr ^ 1) * RAW_LD + gseg * 16];
            const float* pa = &rawAgg[p * RAW_SZ + gr * RAW_LD + gseg * 16];
            __nv_bfloat162* dh = (__nv_bfloat162*)&sAhi[gr * 136 + gseg * 16];
            __nv_bfloat162* dl = (__nv_bfloat162*)&sAlo[gr * 136 + gseg * 16];
#pragma unroll
            for (int c = 0; c < 4; ++c) {
                float4 av = *(const float4*)(pa + 4 * c);
                float4 hv = *(const float4*)(ph + 4 * c);
                float m0 = av.x - hv.x, m1 = av.y - hv.y;
                float m2 = av.z - hv.z, m3 = av.w - hv.w;
                __nv_bfloat162 h01 = pack_hi(m0, m1);
                __nv_bfloat162 h23 = pack_hi(m2, m3);
                dh[2 * c] = h01; dh[2 * c + 1] = h23;
                dl[2 * c] = pack_lo(m0, m1, h01);
                dl[2 * c + 1] = pack_lo(m2, m3, h23);
            }
        }
        __syncthreads();

        // ---- MMA ----
        float acc[2][2][4];
#pragma unroll
        for (int i = 0; i < 2; ++i)
#pragma unroll
            for (int j = 0; j < 2; ++j)
#pragma unroll
                for (int x = 0; x < 4; ++x) acc[i][j][x] = 0.f;

#pragma unroll
        for (int kt = 0; kt < 8; ++kt) {
#pragma unroll
            for (int i = 0; i < 2; ++i) {
                uint32_t ah[4], al[4];
                uint32_t off = (uint32_t)(((i * 16 + arow) * 136 + kt * 16 + acol) * 2);
                ldsm_x4(ah, sAhi_u + off);
                ldsm_x4(al, sAlo_u + off);
#pragma unroll
                for (int j = 0; j < 2; ++j) {
                    mma16816(acc[i][j], ah, Bh[kt][j][0], Bh[kt][j][1]);
                    mma16816(acc[i][j], al, Bh[kt][j][0], Bh[kt][j][1]);
                    mma16816(acc[i][j], ah, Bl[kt][j][0], Bl[kt][j][1]);
                }
            }
        }
        __syncthreads();   // A reads done; sD may overwrite A region

        // ---- stage D fragments into smem ----
        {
            int grow = l >> 2, ncl = (l & 3) * 2;
#pragma unroll
            for (int i = 0; i < 2; ++i) {
                int rloc = i * 16 + grow;
#pragma unroll
                for (int j = 0; j < 2; ++j) {
                    int c = ncb + j * 8 + ncl;
                    *(float2*)&sD[rloc * SD_LD + c] = make_float2(acc[i][j][0], acc[i][j][1]);
                    *(float2*)&sD[(rloc + 8) * SD_LD + c] = make_float2(acc[i][j][2], acc[i][j][3]);
                }
            }
        }
        __syncthreads();

        // ---- coalesced epilogue: relu(D+b) + residual -> g_he (STG.128) ----
        {
            const float* dRow = &sD[gr * SD_LD + gseg * 16];
            const float* hRow = &rawHe[p * RAW_SZ + gr * RAW_LD + gseg * 16];
            const float* bRow = &sBias[gseg * 16];
            float4* out = (float4*)&g_he[(size_t)(e0 + gr) * HD + gseg * 16];
#pragma unroll
            for (int c = 0; c < 4; ++c) {
                float4 d = *(const float4*)(dRow + 4 * c);
                float4 b = *(const float4*)(bRow + 4 * c);
                float4 h = *(const float4*)(hRow + 4 * c);
                float4 o;
                o.x = fmaxf(d.x + b.x, 0.f) + h.x;
                o.y = fmaxf(d.y + b.y, 0.f) + h.y;
                o.z = fmaxf(d.z + b.z, 0.f) + h.z;
                o.w = fmaxf(d.w + b.w, 0.f) + h.w;
                out[c] = o;
            }
        }
        __syncthreads();   // sD/raw reads done before next convert/issue reuse
        sCur = sNext;
        t = tn; p ^= 1;
    }
}

// ---------------------------------------------------------------- agg (MLP-4 CSR gather)
__global__ void __launch_bounds__(256) agg_kernel() {
    int node = (blockIdx.x * blockDim.x + threadIdx.x) >> 5;
    int lane = threadIdx.x & 31;
    if (node >= NN) return;
    int start = __ldg(&g_off[node]);
    int d = __ldg(&g_deg[node]);
    float4 acc = make_float4(0.f, 0.f, 0.f, 0.f);
    int j = 0;
    for (; j + 4 <= d; j += 4) {
        int e0 = __ldg(&g_csr[start + j]);
        int e1 = __ldg(&g_csr[start + j + 1]);
        int e2 = __ldg(&g_csr[start + j + 2]);
        int e3 = __ldg(&g_csr[start + j + 3]);
        float4 v0 = ((const float4*)&g_he[(size_t)e0 * HD])[lane];
        float4 v1 = ((const float4*)&g_he[(size_t)e1 * HD])[lane];
        float4 v2 = ((const float4*)&g_he[(size_t)e2 * HD])[lane];
        float4 v3 = ((const float4*)&g_he[(size_t)e3 * HD])[lane];
        acc.x += v0.x + v1.x + v2.x + v3.x;
        acc.y += v0.y + v1.y + v2.y + v3.y;
        acc.z += v0.z + v1.z + v2.z + v3.z;
        acc.w += v0.w + v1.w + v2.w + v3.w;
    }
    for (; j < d; ++j) {
        int e = __ldg(&g_csr[start + j]);
        float4 v = ((const float4*)&g_he[(size_t)e * HD])[lane];
        acc.x += v.x; acc.y += v.y; acc.z += v.z; acc.w += v.w;
    }
    reinterpret_cast<float4*>(&g_agg[(size_t)node * HD])[lane] = acc;
}

// ---------------------------------------------------------------- wrp / outinit / readout
__global__ void wrp_kernel(const float* __restrict__ Wro, const float* __restrict__ Wpred) {
    __shared__ float sp[HD];
    int i = threadIdx.x;
    sp[i] = Wpred[i];
    __syncthreads();
    float a = 0.f;
    for (int j = 0; j < HD; ++j) a += Wro[(size_t)i * HD + j] * sp[j];
    g_wrp[i] = a;
}
__global__ void outinit_kernel(float* __restrict__ out, const float* __restrict__ bpred) {
    int i = blockIdx.x * blockDim.x + threadIdx.x;
    if (i < NGB) out[i] = bpred[0];
}
__global__ void __launch_bounds__(256) readout_kernel(
    const int* __restrict__ gid, float* __restrict__ out)
{
    int node = (blockIdx.x * blockDim.x + threadIdx.x) >> 5;
    int lane = threadIdx.x & 31;
    if (node >= NN) return;
    int start = __ldg(&g_off[node]);
    int d = __ldg(&g_deg[node]);
    float4 acc = make_float4(0.f, 0.f, 0.f, 0.f);
    int j = 0;
    for (; j + 4 <= d; j += 4) {
        int e0 = __ldg(&g_csr[start + j]);
        int e1 = __ldg(&g_csr[start + j + 1]);
        int e2 = __ldg(&g_csr[start + j + 2]);
        int e3 = __ldg(&g_csr[start + j + 3]);
        float4 v0 = ((const float4*)&g_he[(size_t)e0 * HD])[lane];
        float4 v1 = ((const float4*)&g_he[(size_t)e1 * HD])[lane];
        float4 v2 = ((const float4*)&g_he[(size_t)e2 * HD])[lane];
        float4 v3 = ((const float4*)&g_he[(size_t)e3 * HD])[lane];
        acc.x += v0.x + v1.x + v2.x + v3.x;
        acc.y += v0.y + v1.y + v2.y + v3.y;
        acc.z += v0.z + v1.z + v2.z + v3.z;
        acc.w += v0.w + v1.w + v2.w + v3.w;
    }
    for (; j < d; ++j) {
        int e = __ldg(&g_csr[start + j]);
        float4 v = ((const float4*)&g_he[(size_t)e * HD])[lane];
        acc.x += v.x; acc.y += v.y; acc.z += v.z; acc.w += v.w;
    }
    float4 w = reinterpret_cast<const float4*>(g_wrp)[lane];
    float s = acc.x * w.x + acc.y * w.y + acc.z * w.z + acc.w * w.w;
#pragma unroll
    for (int o = 16; o; o >>= 1) s += __shfl_xor_sync(0xFFFFFFFFu, s, o);
    if (lane == 0) atomicAdd(&out[gid[node]], s);
}

// ---------------------------------------------------------------- launch
extern "C" void kernel_launch(void* const* d_in, const int* in_sizes, int n_in,
                              void* d_out, int out_size)
{
    const float* h      = (const float*)d_in[0];
    const float* e      = (const float*)d_in[1];
    const float* Wemb   = (const float*)d_in[2];
    const float* Winit  = (const float*)d_in[3];
    const float* binit  = (const float*)d_in[4];
    const float* Wlay   = (const float*)d_in[5];
    const float* blay   = (const float*)d_in[6];
    const float* Wro    = (const float*)d_in[7];
    const float* Wpred  = (const float*)d_in[8];
    const float* bpred  = (const float*)d_in[9];
    const int*   src    = (const int*)d_in[10];
    const int*   dst    = (const int*)d_in[11];
    const int*   gid    = (const int*)d_in[12];
    float* out = (float*)d_out;

    cudaFuncSetAttribute(layer_kernel, cudaFuncAttributeMaxDynamicSharedMemorySize, SMEM_LAYER);

    const int nodeWarpBlocks = (NN * 32 + 255) / 256;

    zero_deg_kernel<<<(NN + 255) / 256, 256>>>();                    // 0
    wfuse_kernel<<<1, 128>>>(Wemb, Winit);                           // 1
    z_kernel<<<NN / 64, 128>>>(h, binit);                            // 2
    init_combine_kernel<<<NE / 8, 256>>>(Winit, e, src);             // 3 <- profiled
    deg_count_kernel<<<(NE + 255) / 256, 256>>>(dst);                // 4
    scan_a_kernel<<<NSCAN, SCANB>>>();                               // 5
    scan_b_kernel<<<1, 512>>>();                                     // 6
    scan_c_kernel<<<NSCAN, SCANB>>>();                               // 7
    csr_fill_kernel<<<(NE + 255) / 256, 256>>>(dst);                 // 8

    for (int l = 0; l < 4; ++l) {
        agg_kernel<<<nodeWarpBlocks, 256>>>();
        layer_kernel<<<296, 256, SMEM_LAYER>>>(
            Wlay + (size_t)l * HD * HD, blay + (size_t)l * HD, src);
    }

    wrp_kernel<<<1, HD>>>(Wro, Wpred);
    outinit_kernel<<<(NGB + 255) / 256, 256>>>(out, bpred);
    readout_kernel<<<nodeWarpBlocks, 256>>>(gid, out);
}

// round 15
// speedup vs baseline: 1.2500x; 1.2500x over previous
#include <cuda_runtime.h>
#include <cuda_bf16.h>
#include <mma.h>
#include <cstdint>

using namespace nvcuda;

// D-MPNN on GB300. Round 15: R13 layer/init (proven 2369us) + 2-nodes-per-warp
// agg/readout (tail-imbalance fix). R14's staged epilogue reverted.

#define NN 200000
#define NE 800000
#define HD 128
#define NGB 2000
#define SCANB 512
#define NSCAN ((NN + SCANB - 1) / SCANB)

__device__ float g_x[(size_t)NN * HD];
__device__ float g_he[(size_t)NE * HD];
__device__ float g_agg[(size_t)NN * HD];
__device__ float g_wrp[HD];
__device__ float g_wf[28 * HD];
__device__ int g_deg[NN];
__device__ int g_off[NN];
__device__ int g_cursor[NN];
__device__ int g_csr[NE];
__device__ int g_bsum[NSCAN];

__device__ __forceinline__ __nv_bfloat162 pack_hi(float a, float b) {
    return __nv_bfloat162(__float2bfloat16_rn(a), __float2bfloat16_rn(b));
}
__device__ __forceinline__ __nv_bfloat162 pack_lo(float a, float b, __nv_bfloat162 hi) {
    return __nv_bfloat162(__float2bfloat16_rn(a - __bfloat162float(hi.x)),
                          __float2bfloat16_rn(b - __bfloat162float(hi.y)));
}
__device__ __forceinline__ uint32_t b2u(__nv_bfloat162 v) {
    return *reinterpret_cast<uint32_t*>(&v);
}
__device__ __forceinline__ uint32_t smem_u32(const void* p) {
    uint32_t a;
    asm("{ .reg .u64 t; cvta.to.shared.u64 t, %1; cvt.u32.u64 %0, t; }" : "=r"(a) : "l"(p));
    return a;
}
__device__ __forceinline__ void ldsm_x4(uint32_t* r, uint32_t addr) {
    asm volatile("ldmatrix.sync.aligned.m8n8.x4.shared.b16 {%0,%1,%2,%3}, [%4];"
                 : "=r"(r[0]), "=r"(r[1]), "=r"(r[2]), "=r"(r[3]) : "r"(addr));
}
__device__ __forceinline__ void mma16816(float* d, const uint32_t* a, uint32_t b0, uint32_t b1) {
    asm volatile("mma.sync.aligned.m16n8k16.row.col.f32.bf16.bf16.f32 "
                 "{%0,%1,%2,%3},{%4,%5,%6,%7},{%8,%9},{%0,%1,%2,%3};"
                 : "+f"(d[0]), "+f"(d[1]), "+f"(d[2]), "+f"(d[3])
                 : "r"(a[0]), "r"(a[1]), "r"(a[2]), "r"(a[3]), "r"(b0), "r"(b1));
}
__device__ __forceinline__ void cp16(uint32_t smem, const void* g) {
    asm volatile("cp.async.cg.shared.global [%0], [%1], 16;" :: "r"(smem), "l"(g));
}

// ---------------------------------------------------------------- CSR build
__global__ void zero_deg_kernel() {
    int i = blockIdx.x * blockDim.x + threadIdx.x;
    if (i < NN) g_deg[i] = 0;
}
__global__ void deg_count_kernel(const int* __restrict__ dst) {
    int k = blockIdx.x * blockDim.x + threadIdx.x;
    if (k < NE) atomicAdd(&g_deg[dst[k]], 1);
}
__global__ void scan_a_kernel() {
    __shared__ int s[SCANB];
    int t = threadIdx.x;
    int n = blockIdx.x * SCANB + t;
    s[t] = (n < NN) ? g_deg[n] : 0;
    __syncthreads();
    for (int o = SCANB / 2; o > 0; o >>= 1) {
        if (t < o) s[t] += s[t + o];
        __syncthreads();
    }
    if (t == 0) g_bsum[blockIdx.x] = s[0];
}
__global__ void scan_b_kernel() {
    __shared__ int s[512];
    int t = threadIdx.x;
    int v = (t < NSCAN) ? g_bsum[t] : 0;
    s[t] = v;
    __syncthreads();
    for (int o = 1; o < 512; o <<= 1) {
        int x = (t >= o) ? s[t - o] : 0;
        __syncthreads();
        s[t] += x;
        __syncthreads();
    }
    if (t < NSCAN) g_bsum[t] = s[t] - v;
}
__global__ void scan_c_kernel() {
    __shared__ int s[SCANB];
    int t = threadIdx.x;
    int n = blockIdx.x * SCANB + t;
    int val = (n < NN) ? g_deg[n] : 0;
    s[t] = val;
    __syncthreads();
    for (int o = 1; o < SCANB; o <<= 1) {
        int x = (t >= o) ? s[t - o] : 0;
        __syncthreads();
        s[t] += x;
        __syncthreads();
    }
    if (n < NN) {
        int off = g_bsum[blockIdx.x] + s[t] - val;
        g_off[n] = off;
        g_cursor[n] = off;
    }
}
__global__ void csr_fill_kernel(const int* __restrict__ dst) {
    int k = blockIdx.x * blockDim.x + threadIdx.x;
    if (k < NE) {
        int pos = atomicAdd(&g_cursor[dst[k]], 1);
        g_csr[pos] = k;
    }
}

// ---------------------------------------------------------------- Wf = W_emb @ W_init[:128]
__global__ void __launch_bounds__(128) wfuse_kernel(
    const float* __restrict__ Wemb, const float* __restrict__ Winit)
{
    __shared__ float sWe[28 * 128];
    int n = threadIdx.x;
    for (int i = n; i < 28 * 128; i += 128) sWe[i] = Wemb[i];
    __syncthreads();
    float acc[28];
#pragma unroll
    for (int a = 0; a < 28; ++a) acc[a] = 0.f;
    for (int k = 0; k < 128; ++k) {
        float wv = Winit[k * 128 + n];
#pragma unroll
        for (int a = 0; a < 28; ++a) acc[a] += sWe[a * 128 + k] * wv;
    }
#pragma unroll
    for (int a = 0; a < 28; ++a) g_wf[a * 128 + n] = acc[a];
}

// ---------------------------------------------------------------- Z = h @ Wf + b
__global__ void __launch_bounds__(128) z_kernel(
    const float* __restrict__ h, const float* __restrict__ binit)
{
    __shared__ float sh[64 * 28];
    int n0 = blockIdx.x * 64;
    int tid = threadIdx.x;
    for (int idx = tid; idx < 64 * 28; idx += 128)
        sh[idx] = h[(size_t)n0 * 28 + idx];
    __syncthreads();
    float w[28];
#pragma unroll
    for (int i = 0; i < 28; ++i) w[i] = g_wf[i * HD + tid];
    float b = binit[tid];
    for (int n = 0; n < 64; ++n) {
        float acc = b;
#pragma unroll
        for (int i = 0; i < 28; ++i) acc += sh[n * 28 + i] * w[i];
        g_x[(size_t)(n0 + n) * HD + tid] = acc;
    }
}

// ---------------------------------------------------------------- he0 = relu(Z[src] + e@W2)
__global__ void __launch_bounds__(256) init_combine_kernel(
    const float* __restrict__ Winit, const float* __restrict__ eAttr,
    const int* __restrict__ src)
{
    __shared__ float sW2[6 * 128];
    int tid = threadIdx.x;
    for (int i = tid; i < 6 * 128; i += 256) sW2[i] = Winit[128 * 128 + i];
    __syncthreads();

    int k = blockIdx.x * 8 + (tid >> 5);
    int lane = tid & 31;
    int s = __ldg(&src[k]);
    float ev[6];
#pragma unroll
    for (int j = 0; j < 6; ++j) ev[j] = __ldg(&eAttr[(size_t)k * 6 + j]);
    float4 z = *(const float4*)&g_x[(size_t)s * HD + lane * 4];
#pragma unroll
    for (int j = 0; j < 6; ++j) {
        float4 w2 = *(const float4*)&sW2[j * 128 + lane * 4];
        z.x += ev[j] * w2.x; z.y += ev[j] * w2.y;
        z.z += ev[j] * w2.z; z.w += ev[j] * w2.w;
    }
    z.x = fmaxf(z.x, 0.f); z.y = fmaxf(z.y, 0.f);
    z.z = fmaxf(z.z, 0.f); z.w = fmaxf(z.w, 0.f);
    *(float4*)&g_he[(size_t)k * HD + lane * 4] = z;
}

// ---------------------------------------------------------------- layer GEMM (R13, proven)
#define LTE 32
#define LNT (NE / LTE)                  // 25000
#define RAW_LD 132
#define RAW_SZ (LTE * RAW_LD)
#define LA_SZ (LTE * 136)
#define SMEM_LAYER (4 * RAW_SZ * 4 + 2 * LA_SZ * 2)   // 84,992

__global__ void __launch_bounds__(256, 2) layer_kernel(
    const float* __restrict__ W, const float* __restrict__ bias,
    const int* __restrict__ src)
{
    extern __shared__ char sm[];
    float* rawHe = (float*)sm;
    float* rawAgg = rawHe + 2 * RAW_SZ;
    __nv_bfloat16* sAhi = (__nv_bfloat16*)(rawAgg + 2 * RAW_SZ);
    __nv_bfloat16* sAlo = sAhi + LA_SZ;
    uint32_t rawHe_u = smem_u32(rawHe);
    uint32_t rawAgg_u = smem_u32(rawAgg);
    uint32_t sAhi_u = smem_u32(sAhi);
    uint32_t sAlo_u = smem_u32(sAlo);

    int tid = threadIdx.x;
    int w = tid >> 5, l = tid & 31;
    int ncb = w * 16;

    uint32_t Bh[8][2][2], Bl[8][2][2];
    {
        int kq = (l & 3) * 2;
        int nn = l >> 2;
#pragma unroll
        for (int kt = 0; kt < 8; ++kt)
#pragma unroll
            for (int j = 0; j < 2; ++j) {
                int n = ncb + j * 8 + nn;
#pragma unroll
                for (int hhf = 0; hhf < 2; ++hhf) {
                    int k0 = kt * 16 + hhf * 8 + kq;
                    float w0 = __ldg(&W[k0 * 128 + n]);
                    float w1 = __ldg(&W[(k0 + 1) * 128 + n]);
                    __nv_bfloat162 hi = pack_hi(w0, w1);
                    Bh[kt][j][hhf] = b2u(hi);
                    Bl[kt][j][hhf] = b2u(pack_lo(w0, w1, hi));
                }
            }
    }
    float bs[2][2];
    {
        int ncl = (l & 3) * 2;
#pragma unroll
        for (int j = 0; j < 2; ++j) {
            bs[j][0] = __ldg(&bias[ncb + j * 8 + ncl]);
            bs[j][1] = __ldg(&bias[ncb + j * 8 + ncl + 1]);
        }
    }

    int quad = l >> 3;
    int arow = (l & 7) + ((quad & 1) ? 8 : 0);
    int acol = (quad >= 2) ? 8 : 0;
    int gr = tid >> 3;
    int gseg = tid & 7;

    auto issue = [&](int t, int p, int sIdx) {
        int e0 = t * LTE;
        const float* gh = &g_he[(size_t)(e0 + gr) * HD + gseg * 16];
        const float* ga = &g_agg[(size_t)sIdx * HD + gseg * 16];
        uint32_t dh = rawHe_u + (uint32_t)((p * RAW_SZ + gr * RAW_LD + gseg * 16) * 4);
        uint32_t da = rawAgg_u + (uint32_t)((p * RAW_SZ + gr * RAW_LD + gseg * 16) * 4);
#pragma unroll
        for (int c = 0; c < 4; ++c) {
            cp16(dh + 16 * c, gh + 4 * c);
            cp16(da + 16 * c, ga + 4 * c);
        }
        asm volatile("cp.async.commit_group;" ::: "memory");
    };

    int t = blockIdx.x;
    int p = 0;
    int sCur = (t < LNT) ? __ldg(&src[t * LTE + gr]) : 0;
    int sNext = (t + gridDim.x < LNT) ? __ldg(&src[(t + gridDim.x) * LTE + gr]) : 0;
    if (t < LNT) issue(t, 0, sCur);

    for (; t < LNT; ) {
        int tn = t + gridDim.x;
        int e0 = t * LTE;

        if (tn < LNT) {
            issue(tn, p ^ 1, sNext);
            sNext = (tn + gridDim.x < LNT) ? __ldg(&src[(tn + gridDim.x) * LTE + gr]) : 0;
            asm volatile("cp.async.wait_group 1;" ::: "memory");
        } else {
            asm volatile("cp.async.wait_group 0;" ::: "memory");
        }
        __syncthreads();

        {
            const float* ph = &rawHe[p * RAW_SZ + (gr ^ 1) * RAW_LD + gseg * 16];
            const float* pa = &rawAgg[p * RAW_SZ + gr * RAW_LD + gseg * 16];
            __nv_bfloat162* dh = (__nv_bfloat162*)&sAhi[gr * 136 + gseg * 16];
            __nv_bfloat162* dl = (__nv_bfloat162*)&sAlo[gr * 136 + gseg * 16];
#pragma unroll
            for (int c = 0; c < 4; ++c) {
                float4 av = *(const float4*)(pa + 4 * c);
                float4 hv = *(const float4*)(ph + 4 * c);
                float m0 = av.x - hv.x, m1 = av.y - hv.y;
                float m2 = av.z - hv.z, m3 = av.w - hv.w;
                __nv_bfloat162 h01 = pack_hi(m0, m1);
                __nv_bfloat162 h23 = pack_hi(m2, m3);
                dh[2 * c] = h01; dh[2 * c + 1] = h23;
                dl[2 * c] = pack_lo(m0, m1, h01);
                dl[2 * c + 1] = pack_lo(m2, m3, h23);
            }
        }
        __syncthreads();

        float acc[2][2][4];
#pragma unroll
        for (int i = 0; i < 2; ++i)
#pragma unroll
            for (int j = 0; j < 2; ++j)
#pragma unroll
                for (int x = 0; x < 4; ++x) acc[i][j][x] = 0.f;

#pragma unroll
        for (int kt = 0; kt < 8; ++kt) {
#pragma unroll
            for (int i = 0; i < 2; ++i) {
                uint32_t ah[4], al[4];
                uint32_t off = (uint32_t)(((i * 16 + arow) * 136 + kt * 16 + acol) * 2);
                ldsm_x4(ah, sAhi_u + off);
                ldsm_x4(al, sAlo_u + off);
#pragma unroll
                for (int j = 0; j < 2; ++j) {
                    mma16816(acc[i][j], ah, Bh[kt][j][0], Bh[kt][j][1]);
                    mma16816(acc[i][j], al, Bh[kt][j][0], Bh[kt][j][1]);
                    mma16816(acc[i][j], ah, Bl[kt][j][0], Bl[kt][j][1]);
                }
            }
        }

        int grow = l >> 2, ncl = (l & 3) * 2;
        const float* rhe = &rawHe[p * RAW_SZ];
#pragma unroll
        for (int i = 0; i < 2; ++i) {
            int rloc = i * 16 + grow;
#pragma unroll
            for (int j = 0; j < 2; ++j) {
                int c = ncb + j * 8 + ncl;
                float h00 = rhe[rloc * RAW_LD + c];
                float h01 = rhe[rloc * RAW_LD + c + 1];
                float h10 = rhe[(rloc + 8) * RAW_LD + c];
                float h11 = rhe[(rloc + 8) * RAW_LD + c + 1];
                float2 o0, o1;
                o0.x = fmaxf(acc[i][j][0] + bs[j][0], 0.f) + h00;
                o0.y = fmaxf(acc[i][j][1] + bs[j][1], 0.f) + h01;
                o1.x = fmaxf(acc[i][j][2] + bs[j][0], 0.f) + h10;
                o1.y = fmaxf(acc[i][j][3] + bs[j][1], 0.f) + h11;
                *(float2*)&g_he[(size_t)(e0 + rloc) * HD + c] = o0;
                *(float2*)&g_he[(size_t)(e0 + rloc + 8) * HD + c] = o1;
            }
        }
        __syncthreads();
        sCur = sNext;
        t = tn; p ^= 1;
    }
}

// ---------------------------------------------------------------- agg: 2 nodes per warp
#define AGG_WARPS (NN / 2)   // 100000
__global__ void __launch_bounds__(256) agg_kernel() {
    int wgid = (blockIdx.x * blockDim.x + threadIdx.x) >> 5;
    int lane = threadIdx.x & 31;
    if (wgid >= AGG_WARPS) return;
#pragma unroll
    for (int nn = 0; nn < 2; ++nn) {
        int node = wgid + nn * AGG_WARPS;
        int start = __ldg(&g_off[node]);
        int d = __ldg(&g_deg[node]);
        float4 acc = make_float4(0.f, 0.f, 0.f, 0.f);
        int j = 0;
        for (; j + 4 <= d; j += 4) {
            int e0 = __ldg(&g_csr[start + j]);
            int e1 = __ldg(&g_csr[start + j + 1]);
            int e2 = __ldg(&g_csr[start + j + 2]);
            int e3 = __ldg(&g_csr[start + j + 3]);
            float4 v0 = ((const float4*)&g_he[(size_t)e0 * HD])[lane];
            float4 v1 = ((const float4*)&g_he[(size_t)e1 * HD])[lane];
            float4 v2 = ((const float4*)&g_he[(size_t)e2 * HD])[lane];
            float4 v3 = ((const float4*)&g_he[(size_t)e3 * HD])[lane];
            acc.x += v0.x + v1.x + v2.x + v3.x;
            acc.y += v0.y + v1.y + v2.y + v3.y;
            acc.z += v0.z + v1.z + v2.z + v3.z;
            acc.w += v0.w + v1.w + v2.w + v3.w;
        }
        for (; j < d; ++j) {
            int e = __ldg(&g_csr[start + j]);
            float4 v = ((const float4*)&g_he[(size_t)e * HD])[lane];
            acc.x += v.x; acc.y += v.y; acc.z += v.z; acc.w += v.w;
        }
        reinterpret_cast<float4*>(&g_agg[(size_t)node * HD])[lane] = acc;
    }
}

// ---------------------------------------------------------------- wrp / outinit / readout
__global__ void wrp_kernel(const float* __restrict__ Wro, const float* __restrict__ Wpred) {
    __shared__ float sp[HD];
    int i = threadIdx.x;
    sp[i] = Wpred[i];
    __syncthreads();
    float a = 0.f;
    for (int j = 0; j < HD; ++j) a += Wro[(size_t)i * HD + j] * sp[j];
    g_wrp[i] = a;
}
__global__ void outinit_kernel(float* __restrict__ out, const float* __restrict__ bpred) {
    int i = blockIdx.x * blockDim.x + threadIdx.x;
    if (i < NGB) out[i] = bpred[0];
}
__global__ void __launch_bounds__(256) readout_kernel(
    const int* __restrict__ gid, float* __restrict__ out)
{
    int wgid = (blockIdx.x * blockDim.x + threadIdx.x) >> 5;
    int lane = threadIdx.x & 31;
    if (wgid >= AGG_WARPS) return;
#pragma unroll
    for (int nn = 0; nn < 2; ++nn) {
        int node = wgid + nn * AGG_WARPS;
        int start = __ldg(&g_off[node]);
        int d = __ldg(&g_deg[node]);
        float4 acc = make_float4(0.f, 0.f, 0.f, 0.f);
        int j = 0;
        for (; j + 4 <= d; j += 4) {
            int e0 = __ldg(&g_csr[start + j]);
            int e1 = __ldg(&g_csr[start + j + 1]);
            int e2 = __ldg(&g_csr[start + j + 2]);
            int e3 = __ldg(&g_csr[start + j + 3]);
            float4 v0 = ((const float4*)&g_he[(size_t)e0 * HD])[lane];
            float4 v1 = ((const float4*)&g_he[(size_t)e1 * HD])[lane];
            float4 v2 = ((const float4*)&g_he[(size_t)e2 * HD])[lane];
            float4 v3 = ((const float4*)&g_he[(size_t)e3 * HD])[lane];
            acc.x += v0.x + v1.x + v2.x + v3.x;
            acc.y += v0.y + v1.y + v2.y + v3.y;
            acc.z += v0.z + v1.z + v2.z + v3.z;
            acc.w += v0.w + v1.w + v2.w + v3.w;
        }
        for (; j < d; ++j) {
            int e = __ldg(&g_csr[start + j]);
            float4 v = ((const float4*)&g_he[(size_t)e * HD])[lane];
            acc.x += v.x; acc.y += v.y; acc.z += v.z; acc.w += v.w;
        }
        float4 w = reinterpret_cast<const float4*>(g_wrp)[lane];
        float s = acc.x * w.x + acc.y * w.y + acc.z * w.z + acc.w * w.w;
#pragma unroll
        for (int o = 16; o; o >>= 1) s += __shfl_xor_sync(0xFFFFFFFFu, s, o);
        if (lane == 0) atomicAdd(&out[gid[node]], s);
    }
}

// ---------------------------------------------------------------- launch
extern "C" void kernel_launch(void* const* d_in, const int* in_sizes, int n_in,
                              void* d_out, int out_size)
{
    const float* h      = (const float*)d_in[0];
    const float* e      = (const float*)d_in[1];
    const float* Wemb   = (const float*)d_in[2];
    const float* Winit  = (const float*)d_in[3];
    const float* binit  = (const float*)d_in[4];
    const float* Wlay   = (const float*)d_in[5];
    const float* blay   = (const float*)d_in[6];
    const float* Wro    = (const float*)d_in[7];
    const float* Wpred  = (const float*)d_in[8];
    const float* bpred  = (const float*)d_in[9];
    const int*   src    = (const int*)d_in[10];
    const int*   dst    = (const int*)d_in[11];
    const int*   gid    = (const int*)d_in[12];
    float* out = (float*)d_out;

    cudaFuncSetAttribute(layer_kernel, cudaFuncAttributeMaxDynamicSharedMemorySize, SMEM_LAYER);

    const int aggBlocks = (AGG_WARPS * 32 + 255) / 256;   // 12500

    zero_deg_kernel<<<(NN + 255) / 256, 256>>>();                    // 0
    wfuse_kernel<<<1, 128>>>(Wemb, Winit);                           // 1
    z_kernel<<<NN / 64, 128>>>(h, binit);                            // 2
    init_combine_kernel<<<NE / 8, 256>>>(Winit, e, src);             // 3 <- profiled
    deg_count_kernel<<<(NE + 255) / 256, 256>>>(dst);                // 4
    scan_a_kernel<<<NSCAN, SCANB>>>();                               // 5
    scan_b_kernel<<<1, 512>>>();                                     // 6
    scan_c_kernel<<<NSCAN, SCANB>>>();                               // 7
    csr_fill_kernel<<<(NE + 255) / 256, 256>>>(dst);                 // 8

    for (int l = 0; l < 4; ++l) {
        agg_kernel<<<aggBlocks, 256>>>();
        layer_kernel<<<296, 256, SMEM_LAYER>>>(
            Wlay + (size_t)l * HD * HD, blay + (size_t)l * HD, src);
    }

    wrp_kernel<<<1, HD>>>(Wro, Wpred);
    outinit_kernel<<<(NGB + 255) / 256, 256>>>(out, bpred);
    readout_kernel<<<aggBlocks, 256>>>(gid, out);
}

// round 16
// speedup vs baseline: 1.2568x; 1.0054x over previous
#include <cuda_runtime.h>
#include <cuda_bf16.h>
#include <mma.h>
#include <cstdint>

using namespace nvcuda;

// D-MPNN on GB300. Round 16: R13 base (proven 2369us) with the layer kt-loop
// restructured: all 4 LDSM issued up front per kt, then 12 MMAs (wider
// latency window). agg/readout reverted to R13 1-node-per-warp form.

#define NN 200000
#define NE 800000
#define HD 128
#define NGB 2000
#define SCANB 512
#define NSCAN ((NN + SCANB - 1) / SCANB)

__device__ float g_x[(size_t)NN * HD];
__device__ float g_he[(size_t)NE * HD];
__device__ float g_agg[(size_t)NN * HD];
__device__ float g_wrp[HD];
__device__ float g_wf[28 * HD];
__device__ int g_deg[NN];
__device__ int g_off[NN];
__device__ int g_cursor[NN];
__device__ int g_csr[NE];
__device__ int g_bsum[NSCAN];

__device__ __forceinline__ __nv_bfloat162 pack_hi(float a, float b) {
    return __nv_bfloat162(__float2bfloat16_rn(a), __float2bfloat16_rn(b));
}
__device__ __forceinline__ __nv_bfloat162 pack_lo(float a, float b, __nv_bfloat162 hi) {
    return __nv_bfloat162(__float2bfloat16_rn(a - __bfloat162float(hi.x)),
                          __float2bfloat16_rn(b - __bfloat162float(hi.y)));
}
__device__ __forceinline__ uint32_t b2u(__nv_bfloat162 v) {
    return *reinterpret_cast<uint32_t*>(&v);
}
__device__ __forceinline__ uint32_t smem_u32(const void* p) {
    uint32_t a;
    asm("{ .reg .u64 t; cvta.to.shared.u64 t, %1; cvt.u32.u64 %0, t; }" : "=r"(a) : "l"(p));
    return a;
}
__device__ __forceinline__ void ldsm_x4(uint32_t* r, uint32_t addr) {
    asm volatile("ldmatrix.sync.aligned.m8n8.x4.shared.b16 {%0,%1,%2,%3}, [%4];"
                 : "=r"(r[0]), "=r"(r[1]), "=r"(r[2]), "=r"(r[3]) : "r"(addr));
}
__device__ __forceinline__ void mma16816(float* d, const uint32_t* a, uint32_t b0, uint32_t b1) {
    asm volatile("mma.sync.aligned.m16n8k16.row.col.f32.bf16.bf16.f32 "
                 "{%0,%1,%2,%3},{%4,%5,%6,%7},{%8,%9},{%0,%1,%2,%3};"
                 : "+f"(d[0]), "+f"(d[1]), "+f"(d[2]), "+f"(d[3])
                 : "r"(a[0]), "r"(a[1]), "r"(a[2]), "r"(a[3]), "r"(b0), "r"(b1));
}
__device__ __forceinline__ void cp16(uint32_t smem, const void* g) {
    asm volatile("cp.async.cg.shared.global [%0], [%1], 16;" :: "r"(smem), "l"(g));
}

// ---------------------------------------------------------------- CSR build
__global__ void zero_deg_kernel() {
    int i = blockIdx.x * blockDim.x + threadIdx.x;
    if (i < NN) g_deg[i] = 0;
}
__global__ void deg_count_kernel(const int* __restrict__ dst) {
    int k = blockIdx.x * blockDim.x + threadIdx.x;
    if (k < NE) atomicAdd(&g_deg[dst[k]], 1);
}
__global__ void scan_a_kernel() {
    __shared__ int s[SCANB];
    int t = threadIdx.x;
    int n = blockIdx.x * SCANB + t;
    s[t] = (n < NN) ? g_deg[n] : 0;
    __syncthreads();
    for (int o = SCANB / 2; o > 0; o >>= 1) {
        if (t < o) s[t] += s[t + o];
        __syncthreads();
    }
    if (t == 0) g_bsum[blockIdx.x] = s[0];
}
__global__ void scan_b_kernel() {
    __shared__ int s[512];
    int t = threadIdx.x;
    int v = (t < NSCAN) ? g_bsum[t] : 0;
    s[t] = v;
    __syncthreads();
    for (int o = 1; o < 512; o <<= 1) {
        int x = (t >= o) ? s[t - o] : 0;
        __syncthreads();
        s[t] += x;
        __syncthreads();
    }
    if (t < NSCAN) g_bsum[t] = s[t] - v;
}
__global__ void scan_c_kernel() {
    __shared__ int s[SCANB];
    int t = threadIdx.x;
    int n = blockIdx.x * SCANB + t;
    int val = (n < NN) ? g_deg[n] : 0;
    s[t] = val;
    __syncthreads();
    for (int o = 1; o < SCANB; o <<= 1) {
        int x = (t >= o) ? s[t - o] : 0;
        __syncthreads();
        s[t] += x;
        __syncthreads();
    }
    if (n < NN) {
        int off = g_bsum[blockIdx.x] + s[t] - val;
        g_off[n] = off;
        g_cursor[n] = off;
    }
}
__global__ void csr_fill_kernel(const int* __restrict__ dst) {
    int k = blockIdx.x * blockDim.x + threadIdx.x;
    if (k < NE) {
        int pos = atomicAdd(&g_cursor[dst[k]], 1);
        g_csr[pos] = k;
    }
}

// ---------------------------------------------------------------- Wf = W_emb @ W_init[:128]
__global__ void __launch_bounds__(128) wfuse_kernel(
    const float* __restrict__ Wemb, const float* __restrict__ Winit)
{
    __shared__ float sWe[28 * 128];
    int n = threadIdx.x;
    for (int i = n; i < 28 * 128; i += 128) sWe[i] = Wemb[i];
    __syncthreads();
    float acc[28];
#pragma unroll
    for (int a = 0; a < 28; ++a) acc[a] = 0.f;
    for (int k = 0; k < 128; ++k) {
        float wv = Winit[k * 128 + n];
#pragma unroll
        for (int a = 0; a < 28; ++a) acc[a] += sWe[a * 128 + k] * wv;
    }
#pragma unroll
    for (int a = 0; a < 28; ++a) g_wf[a * 128 + n] = acc[a];
}

// ---------------------------------------------------------------- Z = h @ Wf + b
__global__ void __launch_bounds__(128) z_kernel(
    const float* __restrict__ h, const float* __restrict__ binit)
{
    __shared__ float sh[64 * 28];
    int n0 = blockIdx.x * 64;
    int tid = threadIdx.x;
    for (int idx = tid; idx < 64 * 28; idx += 128)
        sh[idx] = h[(size_t)n0 * 28 + idx];
    __syncthreads();
    float w[28];
#pragma unroll
    for (int i = 0; i < 28; ++i) w[i] = g_wf[i * HD + tid];
    float b = binit[tid];
    for (int n = 0; n < 64; ++n) {
        float acc = b;
#pragma unroll
        for (int i = 0; i < 28; ++i) acc += sh[n * 28 + i] * w[i];
        g_x[(size_t)(n0 + n) * HD + tid] = acc;
    }
}

// ---------------------------------------------------------------- he0 = relu(Z[src] + e@W2)
__global__ void __launch_bounds__(256) init_combine_kernel(
    const float* __restrict__ Winit, const float* __restrict__ eAttr,
    const int* __restrict__ src)
{
    __shared__ float sW2[6 * 128];
    int tid = threadIdx.x;
    for (int i = tid; i < 6 * 128; i += 256) sW2[i] = Winit[128 * 128 + i];
    __syncthreads();

    int k = blockIdx.x * 8 + (tid >> 5);
    int lane = tid & 31;
    int s = __ldg(&src[k]);
    float ev[6];
#pragma unroll
    for (int j = 0; j < 6; ++j) ev[j] = __ldg(&eAttr[(size_t)k * 6 + j]);
    float4 z = *(const float4*)&g_x[(size_t)s * HD + lane * 4];
#pragma unroll
    for (int j = 0; j < 6; ++j) {
        float4 w2 = *(const float4*)&sW2[j * 128 + lane * 4];
        z.x += ev[j] * w2.x; z.y += ev[j] * w2.y;
        z.z += ev[j] * w2.z; z.w += ev[j] * w2.w;
    }
    z.x = fmaxf(z.x, 0.f); z.y = fmaxf(z.y, 0.f);
    z.z = fmaxf(z.z, 0.f); z.w = fmaxf(z.w, 0.f);
    *(float4*)&g_he[(size_t)k * HD + lane * 4] = z;
}

// ---------------------------------------------------------------- layer GEMM
#define LTE 32
#define LNT (NE / LTE)                  // 25000
#define RAW_LD 132
#define RAW_SZ (LTE * RAW_LD)
#define LA_SZ (LTE * 136)
#define SMEM_LAYER (4 * RAW_SZ * 4 + 2 * LA_SZ * 2)   // 84,992

__global__ void __launch_bounds__(256, 2) layer_kernel(
    const float* __restrict__ W, const float* __restrict__ bias,
    const int* __restrict__ src)
{
    extern __shared__ char sm[];
    float* rawHe = (float*)sm;
    float* rawAgg = rawHe + 2 * RAW_SZ;
    __nv_bfloat16* sAhi = (__nv_bfloat16*)(rawAgg + 2 * RAW_SZ);
    __nv_bfloat16* sAlo = sAhi + LA_SZ;
    uint32_t rawHe_u = smem_u32(rawHe);
    uint32_t rawAgg_u = smem_u32(rawAgg);
    uint32_t sAhi_u = smem_u32(sAhi);
    uint32_t sAlo_u = smem_u32(sAlo);

    int tid = threadIdx.x;
    int w = tid >> 5, l = tid & 31;
    int ncb = w * 16;

    uint32_t Bh[8][2][2], Bl[8][2][2];
    {
        int kq = (l & 3) * 2;
        int nn = l >> 2;
#pragma unroll
        for (int kt = 0; kt < 8; ++kt)
#pragma unroll
            for (int j = 0; j < 2; ++j) {
                int n = ncb + j * 8 + nn;
#pragma unroll
                for (int hhf = 0; hhf < 2; ++hhf) {
                    int k0 = kt * 16 + hhf * 8 + kq;
                    float w0 = __ldg(&W[k0 * 128 + n]);
                    float w1 = __ldg(&W[(k0 + 1) * 128 + n]);
                    __nv_bfloat162 hi = pack_hi(w0, w1);
                    Bh[kt][j][hhf] = b2u(hi);
                    Bl[kt][j][hhf] = b2u(pack_lo(w0, w1, hi));
                }
            }
    }
    float bs[2][2];
    {
        int ncl = (l & 3) * 2;
#pragma unroll
        for (int j = 0; j < 2; ++j) {
            bs[j][0] = __ldg(&bias[ncb + j * 8 + ncl]);
            bs[j][1] = __ldg(&bias[ncb + j * 8 + ncl + 1]);
        }
    }

    int quad = l >> 3;
    int arow = (l & 7) + ((quad & 1) ? 8 : 0);
    int acol = (quad >= 2) ? 8 : 0;
    int gr = tid >> 3;
    int gseg = tid & 7;

    auto issue = [&](int t, int p, int sIdx) {
        int e0 = t * LTE;
        const float* gh = &g_he[(size_t)(e0 + gr) * HD + gseg * 16];
        const float* ga = &g_agg[(size_t)sIdx * HD + gseg * 16];
        uint32_t dh = rawHe_u + (uint32_t)((p * RAW_SZ + gr * RAW_LD + gseg * 16) * 4);
        uint32_t da = rawAgg_u + (uint32_t)((p * RAW_SZ + gr * RAW_LD + gseg * 16) * 4);
#pragma unroll
        for (int c = 0; c < 4; ++c) {
            cp16(dh + 16 * c, gh + 4 * c);
            cp16(da + 16 * c, ga + 4 * c);
        }
        asm volatile("cp.async.commit_group;" ::: "memory");
    };

    int t = blockIdx.x;
    int p = 0;
    int sCur = (t < LNT) ? __ldg(&src[t * LTE + gr]) : 0;
    int sNext = (t + gridDim.x < LNT) ? __ldg(&src[(t + gridDim.x) * LTE + gr]) : 0;
    if (t < LNT) issue(t, 0, sCur);

    for (; t < LNT; ) {
        int tn = t + gridDim.x;
        int e0 = t * LTE;

        if (tn < LNT) {
            issue(tn, p ^ 1, sNext);
            sNext = (tn + gridDim.x < LNT) ? __ldg(&src[(tn + gridDim.x) * LTE + gr]) : 0;
            asm volatile("cp.async.wait_group 1;" ::: "memory");
        } else {
            asm volatile("cp.async.wait_group 0;" ::: "memory");
        }
        __syncthreads();

        // ---- convert: m = agg - he(rev) -> A hi/lo ----
        {
            const float* ph = &rawHe[p * RAW_SZ + (gr ^ 1) * RAW_LD + gseg * 16];
            const float* pa = &rawAgg[p * RAW_SZ + gr * RAW_LD + gseg * 16];
            __nv_bfloat162* dh = (__nv_bfloat162*)&sAhi[gr * 136 + gseg * 16];
            __nv_bfloat162* dl = (__nv_bfloat162*)&sAlo[gr * 136 + gseg * 16];
#pragma unroll
            for (int c = 0; c < 4; ++c) {
                float4 av = *(const float4*)(pa + 4 * c);
                float4 hv = *(const float4*)(ph + 4 * c);
                float m0 = av.x - hv.x, m1 = av.y - hv.y;
                float m2 = av.z - hv.z, m3 = av.w - hv.w;
                __nv_bfloat162 h01 = pack_hi(m0, m1);
                __nv_bfloat162 h23 = pack_hi(m2, m3);
                dh[2 * c] = h01; dh[2 * c + 1] = h23;
                dl[2 * c] = pack_lo(m0, m1, h01);
                dl[2 * c + 1] = pack_lo(m2, m3, h23);
            }
        }
        __syncthreads();

        // ---- MMA: 4 LDSM up front per kt, then 12 MMAs ----
        float acc[2][2][4];
#pragma unroll
        for (int i = 0; i < 2; ++i)
#pragma unroll
            for (int j = 0; j < 2; ++j)
#pragma unroll
                for (int x = 0; x < 4; ++x) acc[i][j][x] = 0.f;

#pragma unroll
        for (int kt = 0; kt < 8; ++kt) {
            uint32_t ah[2][4], al[2][4];
#pragma unroll
            for (int i = 0; i < 2; ++i) {
                uint32_t off = (uint32_t)(((i * 16 + arow) * 136 + kt * 16 + acol) * 2);
                ldsm_x4(ah[i], sAhi_u + off);
                ldsm_x4(al[i], sAlo_u + off);
            }
#pragma unroll
            for (int j = 0; j < 2; ++j)
#pragma unroll
                for (int i = 0; i < 2; ++i) {
                    mma16816(acc[i][j], ah[i], Bh[kt][j][0], Bh[kt][j][1]);
                    mma16816(acc[i][j], al[i], Bh[kt][j][0], Bh[kt][j][1]);
                    mma16816(acc[i][j], ah[i], Bl[kt][j][0], Bl[kt][j][1]);
                }
        }

        // ---- epilogue: relu(acc+b) + residual (from staged smem) -> g_he ----
        int grow = l >> 2, ncl = (l & 3) * 2;
        const float* rhe = &rawHe[p * RAW_SZ];
#pragma unroll
        for (int i = 0; i < 2; ++i) {
            int rloc = i * 16 + grow;
#pragma unroll
            for (int j = 0; j < 2; ++j) {
                int c = ncb + j * 8 + ncl;
                float h00 = rhe[rloc * RAW_LD + c];
                float h01 = rhe[rloc * RAW_LD + c + 1];
                float h10 = rhe[(rloc + 8) * RAW_LD + c];
                float h11 = rhe[(rloc + 8) * RAW_LD + c + 1];
                float2 o0, o1;
                o0.x = fmaxf(acc[i][j][0] + bs[j][0], 0.f) + h00;
                o0.y = fmaxf(acc[i][j][1] + bs[j][1], 0.f) + h01;
                o1.x = fmaxf(acc[i][j][2] + bs[j][0], 0.f) + h10;
                o1.y = fmaxf(acc[i][j][3] + bs[j][1], 0.f) + h11;
                *(float2*)&g_he[(size_t)(e0 + rloc) * HD + c] = o0;
                *(float2*)&g_he[(size_t)(e0 + rloc + 8) * HD + c] = o1;
            }
        }
        __syncthreads();
        sCur = sNext;
        t = tn; p ^= 1;
    }
}

// ---------------------------------------------------------------- agg (R13 form)
__global__ void __launch_bounds__(256) agg_kernel() {
    int node = (blockIdx.x * blockDim.x + threadIdx.x) >> 5;
    int lane = threadIdx.x & 31;
    if (node >= NN) return;
    int start = __ldg(&g_off[node]);
    int d = __ldg(&g_deg[node]);
    float4 acc = make_float4(0.f, 0.f, 0.f, 0.f);
    int j = 0;
    for (; j + 4 <= d; j += 4) {
        int e0 = __ldg(&g_csr[start + j]);
        int e1 = __ldg(&g_csr[start + j + 1]);
        int e2 = __ldg(&g_csr[start + j + 2]);
        int e3 = __ldg(&g_csr[start + j + 3]);
        float4 v0 = ((const float4*)&g_he[(size_t)e0 * HD])[lane];
        float4 v1 = ((const float4*)&g_he[(size_t)e1 * HD])[lane];
        float4 v2 = ((const float4*)&g_he[(size_t)e2 * HD])[lane];
        float4 v3 = ((const float4*)&g_he[(size_t)e3 * HD])[lane];
        acc.x += v0.x + v1.x + v2.x + v3.x;
        acc.y += v0.y + v1.y + v2.y + v3.y;
        acc.z += v0.z + v1.z + v2.z + v3.z;
        acc.w += v0.w + v1.w + v2.w + v3.w;
    }
    for (; j < d; ++j) {
        int e = __ldg(&g_csr[start + j]);
        float4 v = ((const float4*)&g_he[(size_t)e * HD])[lane];
        acc.x += v.x; acc.y += v.y; acc.z += v.z; acc.w += v.w;
    }
    reinterpret_cast<float4*>(&g_agg[(size_t)node * HD])[lane] = acc;
}

// ---------------------------------------------------------------- wrp / outinit / readout
__global__ void wrp_kernel(const float* __restrict__ Wro, const float* __restrict__ Wpred) {
    __shared__ float sp[HD];
    int i = threadIdx.x;
    sp[i] = Wpred[i];
    __syncthreads();
    float a = 0.f;
    for (int j = 0; j < HD; ++j) a += Wro[(size_t)i * HD + j] * sp[j];
    g_wrp[i] = a;
}
__global__ void outinit_kernel(float* __restrict__ out, const float* __restrict__ bpred) {
    int i = blockIdx.x * blockDim.x + threadIdx.x;
    if (i < NGB) out[i] = bpred[0];
}
__global__ void __launch_bounds__(256) readout_kernel(
    const int* __restrict__ gid, float* __restrict__ out)
{
    int node = (blockIdx.x * blockDim.x + threadIdx.x) >> 5;
    int lane = threadIdx.x & 31;
    if (node >= NN) return;
    int start = __ldg(&g_off[node]);
    int d = __ldg(&g_deg[node]);
    float4 acc = make_float4(0.f, 0.f, 0.f, 0.f);
    int j = 0;
    for (; j + 4 <= d; j += 4) {
        int e0 = __ldg(&g_csr[start + j]);
        int e1 = __ldg(&g_csr[start + j + 1]);
        int e2 = __ldg(&g_csr[start + j + 2]);
        int e3 = __ldg(&g_csr[start + j + 3]);
        float4 v0 = ((const float4*)&g_he[(size_t)e0 * HD])[lane];
        float4 v1 = ((const float4*)&g_he[(size_t)e1 * HD])[lane];
        float4 v2 = ((const float4*)&g_he[(size_t)e2 * HD])[lane];
        float4 v3 = ((const float4*)&g_he[(size_t)e3 * HD])[lane];
        acc.x += v0.x + v1.x + v2.x + v3.x;
        acc.y += v0.y + v1.y + v2.y + v3.y;
        acc.z += v0.z + v1.z + v2.z + v3.z;
        acc.w += v0.w + v1.w + v2.w + v3.w;
    }
    for (; j < d; ++j) {
        int e = __ldg(&g_csr[start + j]);
        float4 v = ((const float4*)&g_he[(size_t)e * HD])[lane];
        acc.x += v.x; acc.y += v.y; acc.z += v.z; acc.w += v.w;
    }
    float4 w = reinterpret_cast<const float4*>(g_wrp)[lane];
    float s = acc.x * w.x + acc.y * w.y + acc.z * w.z + acc.w * w.w;
#pragma unroll
    for (int o = 16; o; o >>= 1) s += __shfl_xor_sync(0xFFFFFFFFu, s, o);
    if (lane == 0) atomicAdd(&out[gid[node]], s);
}

// ---------------------------------------------------------------- launch
extern "C" void kernel_launch(void* const* d_in, const int* in_sizes, int n_in,
                              void* d_out, int out_size)
{
    const float* h      = (const float*)d_in[0];
    const float* e      = (const float*)d_in[1];
    const float* Wemb   = (const float*)d_in[2];
    const float* Winit  = (const float*)d_in[3];
    const float* binit  = (const float*)d_in[4];
    const float* Wlay   = (const float*)d_in[5];
    const float* blay   = (const float*)d_in[6];
    const float* Wro    = (const float*)d_in[7];
    const float* Wpred  = (const float*)d_in[8];
    const float* bpred  = (const float*)d_in[9];
    const int*   src    = (const int*)d_in[10];
    const int*   dst    = (const int*)d_in[11];
    const int*   gid    = (const int*)d_in[12];
    float* out = (float*)d_out;

    cudaFuncSetAttribute(layer_kernel, cudaFuncAttributeMaxDynamicSharedMemorySize, SMEM_LAYER);

    const int nodeWarpBlocks = (NN * 32 + 255) / 256;

    zero_deg_kernel<<<(NN + 255) / 256, 256>>>();                    // 0
    wfuse_kernel<<<1, 128>>>(Wemb, Winit);                           // 1
    z_kernel<<<NN / 64, 128>>>(h, binit);                            // 2
    init_combine_kernel<<<NE / 8, 256>>>(Winit, e, src);             // 3 <- profiled
    deg_count_kernel<<<(NE + 255) / 256, 256>>>(dst);                // 4
    scan_a_kernel<<<NSCAN, SCANB>>>();                               // 5
    scan_b_kernel<<<1, 512>>>();                                     // 6
    scan_c_kernel<<<NSCAN, SCANB>>>();                               // 7
    csr_fill_kernel<<<(NE + 255) / 256, 256>>>(dst);                 // 8

    for (int l = 0; l < 4; ++l) {
        agg_kernel<<<nodeWarpBlocks, 256>>>();
        layer_kernel<<<296, 256, SMEM_LAYER>>>(
            Wlay + (size_t)l * HD * HD, blay + (size_t)l * HD, src);
    }

    wrp_kernel<<<1, HD>>>(Wro, Wpred);
    outinit_kernel<<<(NGB + 255) / 256, 256>>>(out, bpred);
    readout_kernel<<<nodeWarpBlocks, 256>>>(gid, out);
}